// round 1
// baseline (speedup 1.0000x reference)
#include <cuda_runtime.h>

// ---------------- scratch (static device globals; no allocation) ----------------
__device__ float g_y1[32 * 24 * 32 * 32];   // conv1 raw output (pre-BN)
__device__ float g_y2[32 * 24 * 16 * 16];   // conv2 raw output (pre-BN)
__device__ float g_part1s[24 * 64];         // conv1 per-block channel sums
__device__ float g_part1q[24 * 64];         // conv1 per-block channel sumsq
__device__ float g_part2s[24 * 32];
__device__ float g_part2q[24 * 32];
__device__ float g_ab[96];                  // [0:24) a1, [24:48) c1, [48:72) a2, [72:96) c2

__device__ __forceinline__ float warp_sum(float v) {
#pragma unroll
    for (int o = 16; o > 0; o >>= 1) v += __shfl_down_sync(0xffffffffu, v, o);
    return v;
}

// ---------------- conv1: 3->24 ch, 64x64 -> 32x32, stride 2 pad 1 ----------------
// grid (32, 2, 2): n, output-row-half, co-group(12). block 256.
__global__ __launch_bounds__(256) void conv1_kernel(const float* __restrict__ image,
                                                    const float* __restrict__ w1) {
    const int n = blockIdx.x, half = blockIdx.y;
    const int cb = blockIdx.z * 12;
    const int t = threadIdx.x;

    __shared__ __align__(16) float s_in[3][33][65];   // rows hbase-1..hbase+31, col 0 = zero pad
    __shared__ __align__(16) float s_w[3][3][36];     // [ci][kh][co*3+kw]
    __shared__ float s_red[12][8][2];

    const int hbase = half * 32;

    for (int idx = t; idx < 3 * 33 * 64; idx += 256) {
        int c   = idx / (33 * 64);
        int rem = idx - c * (33 * 64);
        int r   = rem >> 6;
        int w   = rem & 63;
        int hg  = hbase - 1 + r;
        float v = 0.f;
        if (hg >= 0 && hg < 64) v = image[((n * 3 + c) * 64 + hg) * 64 + w];
        s_in[c][r][w + 1] = v;
    }
    for (int idx = t; idx < 99; idx += 256) {
        int c = idx / 33, r = idx % 33;
        s_in[c][r][0] = 0.f;
    }
    for (int idx = t; idx < 324; idx += 256) {
        int co = idx / 27;
        int rem = idx % 27;
        int ci = rem / 9;
        int kh = (rem % 9) / 3;
        int kw = rem % 3;
        s_w[ci][kh][co * 3 + kw] = w1[(cb + co) * 27 + rem];
    }
    __syncthreads();

    const int ho0 = t >> 5, wo0 = t & 31;           // pixel 0 of this thread
    const int ho1 = (t + 256) >> 5, wo1 = (t + 256) & 31;  // pixel 1

    float acc[2][12];
#pragma unroll
    for (int p = 0; p < 2; p++)
#pragma unroll
        for (int co = 0; co < 12; co++) acc[p][co] = 0.f;

#pragma unroll 1
    for (int ci = 0; ci < 3; ci++) {
#pragma unroll 1
        for (int kh = 0; kh < 3; kh++) {
            float wreg[36];
            const float4* wp = reinterpret_cast<const float4*>(&s_w[ci][kh][0]);
#pragma unroll
            for (int q = 0; q < 9; q++) {
                float4 f4 = wp[q];
                wreg[4 * q] = f4.x; wreg[4 * q + 1] = f4.y;
                wreg[4 * q + 2] = f4.z; wreg[4 * q + 3] = f4.w;
            }
            {
                const float* ip = &s_in[ci][2 * ho0 + kh][2 * wo0];
                float v0 = ip[0], v1 = ip[1], v2 = ip[2];
#pragma unroll
                for (int co = 0; co < 12; co++)
                    acc[0][co] += v0 * wreg[co * 3] + v1 * wreg[co * 3 + 1] + v2 * wreg[co * 3 + 2];
            }
            {
                const float* ip = &s_in[ci][2 * ho1 + kh][2 * wo1];
                float v0 = ip[0], v1 = ip[1], v2 = ip[2];
#pragma unroll
                for (int co = 0; co < 12; co++)
                    acc[1][co] += v0 * wreg[co * 3] + v1 * wreg[co * 3 + 1] + v2 * wreg[co * 3 + 2];
            }
        }
    }

    float psum[12], psq[12];
#pragma unroll
    for (int co = 0; co < 12; co++) { psum[co] = 0.f; psq[co] = 0.f; }
#pragma unroll
    for (int p = 0; p < 2; p++) {
        int ho = p ? ho1 : ho0;
        int wo = p ? wo1 : wo0;
#pragma unroll
        for (int co = 0; co < 12; co++) {
            float y = acc[p][co];
            g_y1[((n * 24 + cb + co) * 32 + half * 16 + ho) * 32 + wo] = y;
            psum[co] += y;
            psq[co]  += y * y;
        }
    }

    const int warp = t >> 5, lane = t & 31;
#pragma unroll
    for (int co = 0; co < 12; co++) {
        float rs = warp_sum(psum[co]);
        float rq = warp_sum(psq[co]);
        if (lane == 0) { s_red[co][warp][0] = rs; s_red[co][warp][1] = rq; }
    }
    __syncthreads();
    if (t < 12) {
        float s = 0.f, q = 0.f;
#pragma unroll
        for (int w = 0; w < 8; w++) { s += s_red[t][w][0]; q += s_red[t][w][1]; }
        int pi = n * 2 + half;
        g_part1s[(cb + t) * 64 + pi] = s;
        g_part1q[(cb + t) * 64 + pi] = q;
    }
}

// ---------------- finalize BN stats -> folded affine ----------------
__global__ void finalize_kernel(int stage, const float* __restrict__ gamma,
                                const float* __restrict__ beta) {
    int c = threadIdx.x;
    if (c >= 24) return;
    const float* ps;
    const float* pq;
    int np;
    float invM;
    float* aout;
    float* cout;
    if (stage == 0) {
        ps = g_part1s; pq = g_part1q; np = 64; invM = 1.f / 32768.f;
        aout = g_ab; cout = g_ab + 24;
    } else {
        ps = g_part2s; pq = g_part2q; np = 32; invM = 1.f / 8192.f;
        aout = g_ab + 48; cout = g_ab + 72;
    }
    float s = 0.f, q = 0.f;
    for (int i = 0; i < np; i++) { s += ps[c * np + i]; q += pq[c * np + i]; }
    float mean = s * invM;
    float var  = q * invM - mean * mean;
    float a    = gamma[c] * rsqrtf(var + 1e-5f);
    aout[c] = a;
    cout[c] = beta[c] - mean * a;
}

// ---------------- conv2: 24->24 ch, 32x32 -> 16x16, stride 2 pad 1 ----------------
// Input is relu(a1*y1+c1) applied while staging to smem. grid (32,4): n, co-group(6).
__global__ __launch_bounds__(256) void conv2_kernel(const float* __restrict__ w2) {
    const int n = blockIdx.x;
    const int cb = blockIdx.y * 6;
    const int t = threadIdx.x;

    __shared__ __align__(16) float s_in[8][33][33];  // row0/col0 zero pad
    __shared__ __align__(16) float s_w[8][56];       // [ci8][c6*9 + kh*3 + kw]
    __shared__ float s_a[24], s_c[24];
    __shared__ float s_red[6][8][2];

    if (t < 24) { s_a[t] = g_ab[t]; s_c[t] = g_ab[24 + t]; }

    const int ho = t >> 4, wo = t & 15;
    float acc[6];
#pragma unroll
    for (int c6 = 0; c6 < 6; c6++) acc[c6] = 0.f;

#pragma unroll 1
    for (int ph = 0; ph < 3; ph++) {
        const int cc = ph * 8;
        __syncthreads();  // covers s_a store on first iter, s_in reuse after
        for (int idx = t; idx < 264; idx += 256) {
            int ci = idx / 33, k = idx % 33;
            s_in[ci][0][k] = 0.f;
            s_in[ci][k][0] = 0.f;
        }
        for (int idx = t; idx < 8192; idx += 256) {
            int ci8 = idx >> 10;
            int rem = idx & 1023;
            int h = rem >> 5, w = rem & 31;
            float y = g_y1[((n * 24 + cc + ci8) * 32 + h) * 32 + w];
            float f = fmaxf(fmaf(s_a[cc + ci8], y, s_c[cc + ci8]), 0.f);
            s_in[ci8][h + 1][w + 1] = f;
        }
        for (int idx = t; idx < 432; idx += 256) {
            int c6 = idx / 72;
            int r = idx % 72;
            int ci8 = r / 9, k = r % 9;
            s_w[ci8][c6 * 9 + k] = w2[((cb + c6) * 24 + cc + ci8) * 9 + k];
        }
        __syncthreads();

#pragma unroll 1
        for (int ci8 = 0; ci8 < 8; ci8++) {
            float wreg[56];
            const float4* wp = reinterpret_cast<const float4*>(&s_w[ci8][0]);
#pragma unroll
            for (int q = 0; q < 14; q++) {
                float4 f4 = wp[q];
                wreg[4 * q] = f4.x; wreg[4 * q + 1] = f4.y;
                wreg[4 * q + 2] = f4.z; wreg[4 * q + 3] = f4.w;
            }
#pragma unroll
            for (int kh = 0; kh < 3; kh++) {
                const float* ip = &s_in[ci8][2 * ho + kh][2 * wo];
                float v0 = ip[0], v1 = ip[1], v2 = ip[2];
#pragma unroll
                for (int c6 = 0; c6 < 6; c6++)
                    acc[c6] += v0 * wreg[c6 * 9 + kh * 3] +
                               v1 * wreg[c6 * 9 + kh * 3 + 1] +
                               v2 * wreg[c6 * 9 + kh * 3 + 2];
            }
        }
    }

#pragma unroll
    for (int c6 = 0; c6 < 6; c6++)
        g_y2[((n * 24 + cb + c6) * 16 + ho) * 16 + wo] = acc[c6];

    const int warp = t >> 5, lane = t & 31;
#pragma unroll
    for (int c6 = 0; c6 < 6; c6++) {
        float rs = warp_sum(acc[c6]);
        float rq = warp_sum(acc[c6] * acc[c6]);
        if (lane == 0) { s_red[c6][warp][0] = rs; s_red[c6][warp][1] = rq; }
    }
    __syncthreads();
    if (t < 6) {
        float s = 0.f, q = 0.f;
#pragma unroll
        for (int w = 0; w < 8; w++) { s += s_red[t][w][0]; q += s_red[t][w][1]; }
        g_part2s[(cb + t) * 32 + n] = s;
        g_part2q[(cb + t) * 32 + n] = q;
    }
}

// ---------------- head: spatial sum -> relations -> fc1(relu) -> fc2 ----------------
// grid 32 (n), block 256.
__global__ __launch_bounds__(256) void head_kernel(
    const float* __restrict__ ques, const float* __restrict__ w_rel,
    const float* __restrict__ b_rel, const float* __restrict__ w_fc1,
    const float* __restrict__ b_fc1, const float* __restrict__ w_fc2,
    const float* __restrict__ b_fc2, float* __restrict__ out) {
    const int n = blockIdx.x;
    const int t = threadIdx.x;

    __shared__ float s_q[128];
    __shared__ float s_s[26];
    __shared__ float s_part[24][8];
    __shared__ float s_r[128];
    __shared__ __align__(16) float s_h[1024];
    __shared__ float s_o[8][2];
    __shared__ float s_a2[24], s_c2[24];

    if (t < 128) s_q[t] = ques[n * 128 + t];
    if (t >= 128 && t < 152) {
        int c = t - 128;
        s_a2[c] = g_ab[48 + c];
        s_c2[c] = g_ab[72 + c];
    }
    __syncthreads();

    // spatial sums of relu(bn2(y2)) -> s[0..23]; coord sums (exactly ~0) -> 0
    if (t < 192) {
        int c = t >> 3, g = t & 7;
        const float* yp = &g_y2[(n * 24 + c) * 256 + g * 32];
        float a = s_a2[c], cc = s_c2[c];
        float acc = 0.f;
#pragma unroll
        for (int i = 0; i < 32; i++) acc += fmaxf(fmaf(a, yp[i], cc), 0.f);
        s_part[c][g] = acc;
    }
    __syncthreads();
    if (t < 26) {
        float s = 0.f;
        if (t < 24) {
#pragma unroll
            for (int g = 0; g < 8; g++) s += s_part[t][g];
        }
        s_s[t] = s;
    }
    __syncthreads();

    // relations[j] = 256 * s·(Wi+Wj)[:,j] + 65536 * (q·Wq[:,j] + b_rel[j])
    if (t < 128) {
        const int j = t;
        float r1 = 0.f;
#pragma unroll
        for (int k = 0; k < 26; k++)
            r1 += s_s[k] * (w_rel[k * 128 + j] + w_rel[(26 + k) * 128 + j]);
        float r2 = b_rel[j];
#pragma unroll 4
        for (int q = 0; q < 128; q++)
            r2 = fmaf(s_q[q], w_rel[(52 + q) * 128 + j], r2);
        s_r[j] = 256.f * r1 + 65536.f * r2;
    }
    __syncthreads();

    // h = relu(r @ w_fc1 + b_fc1): each thread 4 consecutive outputs (float4)
    {
        float4 accv = *reinterpret_cast<const float4*>(&b_fc1[t * 4]);
#pragma unroll 4
        for (int j = 0; j < 128; j++) {
            float rv = s_r[j];
            float4 wv = *reinterpret_cast<const float4*>(&w_fc1[j * 1024 + t * 4]);
            accv.x = fmaf(rv, wv.x, accv.x);
            accv.y = fmaf(rv, wv.y, accv.y);
            accv.z = fmaf(rv, wv.z, accv.z);
            accv.w = fmaf(rv, wv.w, accv.w);
        }
        float4 hv;
        hv.x = fmaxf(accv.x, 0.f);
        hv.y = fmaxf(accv.y, 0.f);
        hv.z = fmaxf(accv.z, 0.f);
        hv.w = fmaxf(accv.w, 0.f);
        *reinterpret_cast<float4*>(&s_h[t * 4]) = hv;
    }
    __syncthreads();

    // out = h @ w_fc2 + b_fc2
    {
        float p0 = 0.f, p1 = 0.f;
#pragma unroll 4
        for (int m = t; m < 1024; m += 256) {
            float hv = s_h[m];
            float2 wv = *reinterpret_cast<const float2*>(&w_fc2[m * 2]);
            p0 = fmaf(hv, wv.x, p0);
            p1 = fmaf(hv, wv.y, p1);
        }
        p0 = warp_sum(p0);
        p1 = warp_sum(p1);
        const int warp = t >> 5, lane = t & 31;
        if (lane == 0) { s_o[warp][0] = p0; s_o[warp][1] = p1; }
    }
    __syncthreads();
    if (t == 0) {
        float o0 = b_fc2[0], o1 = b_fc2[1];
#pragma unroll
        for (int w = 0; w < 8; w++) { o0 += s_o[w][0]; o1 += s_o[w][1]; }
        out[n * 2 + 0] = o0;
        out[n * 2 + 1] = o1;
    }
}

// ---------------- launch ----------------
extern "C" void kernel_launch(void* const* d_in, const int* in_sizes, int n_in,
                              void* d_out, int out_size) {
    (void)in_sizes; (void)n_in; (void)out_size;
    const float* image   = (const float*)d_in[0];
    const float* ques    = (const float*)d_in[1];
    const float* conv1_w = (const float*)d_in[2];
    // d_in[3] conv1_b: zero, cancels through BN
    const float* bn1_g   = (const float*)d_in[4];
    const float* bn1_b   = (const float*)d_in[5];
    const float* conv2_w = (const float*)d_in[6];
    // d_in[7] conv2_b: zero, cancels through BN
    const float* bn2_g   = (const float*)d_in[8];
    const float* bn2_b   = (const float*)d_in[9];
    const float* w_rel   = (const float*)d_in[10];
    const float* b_rel   = (const float*)d_in[11];
    const float* w_fc1   = (const float*)d_in[12];
    const float* b_fc1   = (const float*)d_in[13];
    const float* w_fc2   = (const float*)d_in[14];
    const float* b_fc2   = (const float*)d_in[15];
    float* out = (float*)d_out;

    conv1_kernel<<<dim3(32, 2, 2), 256>>>(image, conv1_w);
    finalize_kernel<<<1, 32>>>(0, bn1_g, bn1_b);
    conv2_kernel<<<dim3(32, 4), 256>>>(conv2_w);
    finalize_kernel<<<1, 32>>>(1, bn2_g, bn2_b);
    head_kernel<<<32, 256>>>(ques, w_rel, b_rel, w_fc1, b_fc1, w_fc2, b_fc2, out);
}

// round 2
// speedup vs baseline: 1.0739x; 1.0739x over previous
#include <cuda_runtime.h>

// ---------------- scratch (static device globals; no allocation) ----------------
__device__ float g_y1[32 * 24 * 32 * 32];   // conv1 raw output (pre-BN)
__device__ float g_y2[32 * 24 * 16 * 16];   // conv2 raw output (pre-BN)
__device__ float g_part1s[24 * 64];         // conv1 per-block channel sums
__device__ float g_part1q[24 * 64];
__device__ float g_part2s[24 * 32];
__device__ float g_part2q[24 * 32];
__device__ unsigned g_bar_count;            // zero-initialized, self-cleaning
__device__ volatile unsigned g_bar_gen;

#define NBLOCKS 128

__device__ __forceinline__ float warp_sum(float v) {
#pragma unroll
    for (int o = 16; o > 0; o >>= 1) v += __shfl_down_sync(0xffffffffu, v, o);
    return v;
}

// Software grid barrier: all NBLOCKS blocks are guaranteed co-resident
// (1 block/SM max by smem, 128 <= 148 SMs).
__device__ __forceinline__ void grid_barrier() {
    __syncthreads();
    if (threadIdx.x == 0) {
        __threadfence();                       // release prior writes
        unsigned gen = g_bar_gen;
        unsigned ticket = atomicAdd(&g_bar_count, 1u);
        if (ticket == NBLOCKS - 1) {
            g_bar_count = 0;
            __threadfence();
            g_bar_gen = gen + 1;               // flip generation
        } else {
            while (g_bar_gen == gen) { __nanosleep(64); }
        }
        __threadfence();                       // acquire
    }
    __syncthreads();
}

// Distributed BN finalize: every block computes the 24 folded affine consts itself.
__device__ __forceinline__ void compute_bn24(const float* __restrict__ ps,
                                             const float* __restrict__ pq,
                                             int np, float invM,
                                             const float* __restrict__ gamma,
                                             const float* __restrict__ beta,
                                             float* s_a, float* s_c, int t) {
    if (t < 192) {
        int c = t >> 3, g = t & 7;
        float s = 0.f, q = 0.f;
        for (int i = g; i < np; i += 8) { s += ps[c * np + i]; q += pq[c * np + i]; }
#pragma unroll
        for (int o = 4; o > 0; o >>= 1) {
            s += __shfl_down_sync(0xffffffffu, s, o, 8);
            q += __shfl_down_sync(0xffffffffu, q, o, 8);
        }
        if (g == 0) {
            float mean = s * invM;
            float var  = q * invM - mean * mean;
            float a    = gamma[c] * rsqrtf(var + 1e-5f);
            s_a[c] = a;
            s_c[c] = beta[c] - mean * a;
        }
    }
}

// ------------------------- fused persistent kernel -------------------------
// smem union carve (floats):
//  conv1: in1 @0 (3*33*65=6435), w1 @6448 (3*3*36=324), red1 @6784 (12*8*2)
//  conv2: in2 @0 (8*33*33=8712), w2 @8720 (8*56=448), a @9168(24), c @9192(24),
//         red2 @9216 (6*8*2)
//  head:  q @0(128), a2 @128(24), c2 @152(24), part @176(24*8), s @368(32),
//         r @400(128), h @528(1024), o @1552(16)
__global__ __launch_bounds__(256) void fused_kernel(
    const float* __restrict__ image, const float* __restrict__ w1,
    const float* __restrict__ bn1_g, const float* __restrict__ bn1_b,
    const float* __restrict__ w2, const float* __restrict__ bn2_g,
    const float* __restrict__ bn2_b, const float* __restrict__ ques,
    const float* __restrict__ w_rel, const float* __restrict__ b_rel,
    const float* __restrict__ w_fc1, const float* __restrict__ b_fc1,
    const float* __restrict__ w_fc2, const float* __restrict__ b_fc2,
    float* __restrict__ out) {

    __shared__ __align__(16) float smem[9408];
    const int bid = blockIdx.x;
    const int t = threadIdx.x;
    const int warp = t >> 5, lane = t & 31;

    // ============================ PHASE 1: conv1 ============================
    // bid -> n = bid>>2, half = (bid>>1)&1, cb = (bid&1)*12
    {
        const int n = bid >> 2, half = (bid >> 1) & 1;
        const int cb = (bid & 1) * 12;
        float* s_in = smem;                      // [3][33][65]
        float* s_w  = smem + 6448;               // [ci*3+kh][36]
        float* s_rd = smem + 6784;               // [co][8][2]

        const int hbase = half * 32;
        for (int idx = t; idx < 3 * 33 * 64; idx += 256) {
            int c   = idx / (33 * 64);
            int rem = idx - c * (33 * 64);
            int r   = rem >> 6;
            int w   = rem & 63;
            int hg  = hbase - 1 + r;
            float v = 0.f;
            if (hg >= 0 && hg < 64) v = image[((n * 3 + c) * 64 + hg) * 64 + w];
            s_in[c * 2145 + r * 65 + w + 1] = v;
        }
        for (int idx = t; idx < 99; idx += 256) {
            int c = idx / 33, r = idx % 33;
            s_in[c * 2145 + r * 65] = 0.f;
        }
        for (int idx = t; idx < 324; idx += 256) {
            int co = idx / 27;
            int rem = idx % 27;
            int ci = rem / 9;
            int kh = (rem % 9) / 3;
            int kw = rem % 3;
            s_w[(ci * 3 + kh) * 36 + co * 3 + kw] = w1[(cb + co) * 27 + rem];
        }
        __syncthreads();

        const int ho0 = t >> 5, wo0 = t & 31;
        const int ho1 = (t + 256) >> 5, wo1 = (t + 256) & 31;

        float acc[2][12];
#pragma unroll
        for (int p = 0; p < 2; p++)
#pragma unroll
            for (int co = 0; co < 12; co++) acc[p][co] = 0.f;

#pragma unroll 1
        for (int ci = 0; ci < 3; ci++) {
#pragma unroll 1
            for (int kh = 0; kh < 3; kh++) {
                float wreg[36];
                const float4* wp = reinterpret_cast<const float4*>(&s_w[(ci * 3 + kh) * 36]);
#pragma unroll
                for (int q = 0; q < 9; q++) {
                    float4 f4 = wp[q];
                    wreg[4 * q] = f4.x; wreg[4 * q + 1] = f4.y;
                    wreg[4 * q + 2] = f4.z; wreg[4 * q + 3] = f4.w;
                }
                {
                    const float* ip = &s_in[ci * 2145 + (2 * ho0 + kh) * 65 + 2 * wo0];
                    float v0 = ip[0], v1 = ip[1], v2 = ip[2];
#pragma unroll
                    for (int co = 0; co < 12; co++)
                        acc[0][co] += v0 * wreg[co * 3] + v1 * wreg[co * 3 + 1] + v2 * wreg[co * 3 + 2];
                }
                {
                    const float* ip = &s_in[ci * 2145 + (2 * ho1 + kh) * 65 + 2 * wo1];
                    float v0 = ip[0], v1 = ip[1], v2 = ip[2];
#pragma unroll
                    for (int co = 0; co < 12; co++)
                        acc[1][co] += v0 * wreg[co * 3] + v1 * wreg[co * 3 + 1] + v2 * wreg[co * 3 + 2];
                }
            }
        }

        float psum[12], psq[12];
#pragma unroll
        for (int co = 0; co < 12; co++) { psum[co] = 0.f; psq[co] = 0.f; }
#pragma unroll
        for (int p = 0; p < 2; p++) {
            int ho = p ? ho1 : ho0;
            int wo = p ? wo1 : wo0;
#pragma unroll
            for (int co = 0; co < 12; co++) {
                float y = acc[p][co];
                g_y1[((n * 24 + cb + co) * 32 + half * 16 + ho) * 32 + wo] = y;
                psum[co] += y;
                psq[co]  += y * y;
            }
        }

#pragma unroll
        for (int co = 0; co < 12; co++) {
            float rs = warp_sum(psum[co]);
            float rq = warp_sum(psq[co]);
            if (lane == 0) { s_rd[co * 16 + warp * 2] = rs; s_rd[co * 16 + warp * 2 + 1] = rq; }
        }
        __syncthreads();
        if (t < 12) {
            float s = 0.f, q = 0.f;
#pragma unroll
            for (int w = 0; w < 8; w++) { s += s_rd[t * 16 + w * 2]; q += s_rd[t * 16 + w * 2 + 1]; }
            int pi = n * 2 + half;
            g_part1s[(cb + t) * 64 + pi] = s;
            g_part1q[(cb + t) * 64 + pi] = q;
        }
    }

    grid_barrier();

    // ============================ PHASE 2: conv2 ============================
    // bid -> n = bid>>2, cb = (bid&3)*6
    {
        const int n = bid >> 2;
        const int cb = (bid & 3) * 6;
        float* s_in = smem;                      // [8][33][33]
        float* s_w  = smem + 8720;               // [ci8][56]
        float* s_a  = smem + 9168;
        float* s_c  = smem + 9192;
        float* s_rd = smem + 9216;               // [c6][8][2]

        compute_bn24(g_part1s, g_part1q, 64, 1.f / 32768.f, bn1_g, bn1_b, s_a, s_c, t);

        const int ho = t >> 4, wo = t & 15;
        float acc[6];
#pragma unroll
        for (int c6 = 0; c6 < 6; c6++) acc[c6] = 0.f;

#pragma unroll 1
        for (int ph = 0; ph < 3; ph++) {
            const int cc = ph * 8;
            __syncthreads();   // covers BN consts first iter, s_in reuse after
            for (int idx = t; idx < 264; idx += 256) {
                int ci = idx / 33, k = idx % 33;
                s_in[ci * 1089 + k] = 0.f;       // row 0
                s_in[ci * 1089 + k * 33] = 0.f;  // col 0
            }
            for (int idx = t; idx < 8192; idx += 256) {
                int ci8 = idx >> 10;
                int rem = idx & 1023;
                int h = rem >> 5, w = rem & 31;
                float y = g_y1[((n * 24 + cc + ci8) * 32 + h) * 32 + w];
                float f = fmaxf(fmaf(s_a[cc + ci8], y, s_c[cc + ci8]), 0.f);
                s_in[ci8 * 1089 + (h + 1) * 33 + (w + 1)] = f;
            }
            for (int idx = t; idx < 432; idx += 256) {
                int c6 = idx / 72;
                int r = idx % 72;
                int ci8 = r / 9, k = r % 9;
                s_w[ci8 * 56 + c6 * 9 + k] = w2[((cb + c6) * 24 + cc + ci8) * 9 + k];
            }
            __syncthreads();

#pragma unroll 1
            for (int ci8 = 0; ci8 < 8; ci8++) {
                float wreg[56];
                const float4* wp = reinterpret_cast<const float4*>(&s_w[ci8 * 56]);
#pragma unroll
                for (int q = 0; q < 14; q++) {
                    float4 f4 = wp[q];
                    wreg[4 * q] = f4.x; wreg[4 * q + 1] = f4.y;
                    wreg[4 * q + 2] = f4.z; wreg[4 * q + 3] = f4.w;
                }
#pragma unroll
                for (int kh = 0; kh < 3; kh++) {
                    const float* ip = &s_in[ci8 * 1089 + (2 * ho + kh) * 33 + 2 * wo];
                    float v0 = ip[0], v1 = ip[1], v2 = ip[2];
#pragma unroll
                    for (int c6 = 0; c6 < 6; c6++)
                        acc[c6] += v0 * wreg[c6 * 9 + kh * 3] +
                                   v1 * wreg[c6 * 9 + kh * 3 + 1] +
                                   v2 * wreg[c6 * 9 + kh * 3 + 2];
                }
            }
        }

#pragma unroll
        for (int c6 = 0; c6 < 6; c6++)
            g_y2[((n * 24 + cb + c6) * 16 + ho) * 16 + wo] = acc[c6];

#pragma unroll
        for (int c6 = 0; c6 < 6; c6++) {
            float rs = warp_sum(acc[c6]);
            float rq = warp_sum(acc[c6] * acc[c6]);
            if (lane == 0) { s_rd[c6 * 16 + warp * 2] = rs; s_rd[c6 * 16 + warp * 2 + 1] = rq; }
        }
        __syncthreads();
        if (t < 6) {
            float s = 0.f, q = 0.f;
#pragma unroll
            for (int w = 0; w < 8; w++) { s += s_rd[t * 16 + w * 2]; q += s_rd[t * 16 + w * 2 + 1]; }
            g_part2s[(cb + t) * 32 + n] = s;
            g_part2q[(cb + t) * 32 + n] = q;
        }
    }

    grid_barrier();

    // ============================= PHASE 3: head ============================
    if (bid >= 32) return;
    {
        const int n = bid;
        float* s_q    = smem;            // 128
        float* s_a2   = smem + 128;      // 24
        float* s_c2   = smem + 152;      // 24
        float* s_part = smem + 176;      // 24*8
        float* s_s    = smem + 368;      // 26 (pad 32)
        float* s_r    = smem + 400;      // 128
        float* s_h    = smem + 528;      // 1024 (16B aligned)
        float* s_o    = smem + 1552;     // 16

        compute_bn24(g_part2s, g_part2q, 32, 1.f / 8192.f, bn2_g, bn2_b, s_a2, s_c2, t);
        if (t >= 192 && t < 192 + 64) {
            int j = t - 192;
            s_q[j * 2]     = ques[n * 128 + j * 2];
            s_q[j * 2 + 1] = ques[n * 128 + j * 2 + 1];
        }
        __syncthreads();

        // spatial sums of relu(bn2(y2)) -> s[0..23]; coord sums ~0 -> 0
        if (t < 192) {
            int c = t >> 3, g = t & 7;
            const float* yp = &g_y2[(n * 24 + c) * 256 + g * 32];
            float a = s_a2[c], cc = s_c2[c];
            float acc = 0.f;
#pragma unroll
            for (int i = 0; i < 32; i++) acc += fmaxf(fmaf(a, yp[i], cc), 0.f);
            s_part[c * 8 + g] = acc;
        }
        __syncthreads();
        if (t < 26) {
            float s = 0.f;
            if (t < 24) {
#pragma unroll
                for (int g = 0; g < 8; g++) s += s_part[t * 8 + g];
            }
            s_s[t] = s;
        }
        __syncthreads();

        // relations[j] = 256 * s.(Wi+Wj)[:,j] + 65536 * (q.Wq[:,j] + b_rel[j])
        if (t < 128) {
            const int j = t;
            float r1 = 0.f;
#pragma unroll
            for (int k = 0; k < 26; k++)
                r1 += s_s[k] * (w_rel[k * 128 + j] + w_rel[(26 + k) * 128 + j]);
            float r2 = b_rel[j];
#pragma unroll 4
            for (int q = 0; q < 128; q++)
                r2 = fmaf(s_q[q], w_rel[(52 + q) * 128 + j], r2);
            s_r[j] = 256.f * r1 + 65536.f * r2;
        }
        __syncthreads();

        // h = relu(r @ w_fc1 + b_fc1): thread -> 4 consecutive outputs
        {
            float4 accv = *reinterpret_cast<const float4*>(&b_fc1[t * 4]);
#pragma unroll 4
            for (int j = 0; j < 128; j++) {
                float rv = s_r[j];
                float4 wv = *reinterpret_cast<const float4*>(&w_fc1[j * 1024 + t * 4]);
                accv.x = fmaf(rv, wv.x, accv.x);
                accv.y = fmaf(rv, wv.y, accv.y);
                accv.z = fmaf(rv, wv.z, accv.z);
                accv.w = fmaf(rv, wv.w, accv.w);
            }
            float4 hv;
            hv.x = fmaxf(accv.x, 0.f);
            hv.y = fmaxf(accv.y, 0.f);
            hv.z = fmaxf(accv.z, 0.f);
            hv.w = fmaxf(accv.w, 0.f);
            *reinterpret_cast<float4*>(&s_h[t * 4]) = hv;
        }
        __syncthreads();

        // out = h @ w_fc2 + b_fc2
        {
            float p0 = 0.f, p1 = 0.f;
#pragma unroll 4
            for (int m = t; m < 1024; m += 256) {
                float hv = s_h[m];
                float2 wv = *reinterpret_cast<const float2*>(&w_fc2[m * 2]);
                p0 = fmaf(hv, wv.x, p0);
                p1 = fmaf(hv, wv.y, p1);
            }
            p0 = warp_sum(p0);
            p1 = warp_sum(p1);
            if (lane == 0) { s_o[warp * 2] = p0; s_o[warp * 2 + 1] = p1; }
        }
        __syncthreads();
        if (t == 0) {
            float o0 = b_fc2[0], o1 = b_fc2[1];
#pragma unroll
            for (int w = 0; w < 8; w++) { o0 += s_o[w * 2]; o1 += s_o[w * 2 + 1]; }
            out[n * 2 + 0] = o0;
            out[n * 2 + 1] = o1;
        }
    }
}

// ---------------- launch ----------------
extern "C" void kernel_launch(void* const* d_in, const int* in_sizes, int n_in,
                              void* d_out, int out_size) {
    (void)in_sizes; (void)n_in; (void)out_size;
    const float* image   = (const float*)d_in[0];
    const float* ques    = (const float*)d_in[1];
    const float* conv1_w = (const float*)d_in[2];
    const float* bn1_g   = (const float*)d_in[4];
    const float* bn1_b   = (const float*)d_in[5];
    const float* conv2_w = (const float*)d_in[6];
    const float* bn2_g   = (const float*)d_in[8];
    const float* bn2_b   = (const float*)d_in[9];
    const float* w_rel   = (const float*)d_in[10];
    const float* b_rel   = (const float*)d_in[11];
    const float* w_fc1   = (const float*)d_in[12];
    const float* b_fc1   = (const float*)d_in[13];
    const float* w_fc2   = (const float*)d_in[14];
    const float* b_fc2   = (const float*)d_in[15];
    float* out = (float*)d_out;

    fused_kernel<<<NBLOCKS, 256>>>(image, conv1_w, bn1_g, bn1_b,
                                   conv2_w, bn2_g, bn2_b,
                                   ques, w_rel, b_rel,
                                   w_fc1, b_fc1, w_fc2, b_fc2, out);
}